// round 1
// baseline (speedup 1.0000x reference)
#include <cuda_runtime.h>
#include <math.h>

#define B_    8
#define D_    512
#define H_    8
#define DH_   64
#define L_    6
#define DFF_  2048
#define CIN_  2048
#define SEQ_  912
#define NTOK_ 911
#define DMLP_ 1024

// ---------------- scratch (static device globals; allocation-free) ----------
__device__ float g_A[(size_t)B_ * NTOK_ * CIN_];     // transposed features
__device__ float g_add[(size_t)NTOK_ * D_];          // conv_b + chan_emb + pos_emb per token
__device__ float g_x[(size_t)B_ * SEQ_ * D_];
__device__ float g_tmp[(size_t)B_ * SEQ_ * D_];
__device__ float g_q[(size_t)B_ * SEQ_ * D_];        // (B,H,S,DH)
__device__ float g_k[(size_t)B_ * SEQ_ * D_];        // (B,H,S,DH)
__device__ float g_v[(size_t)B_ * SEQ_ * D_];        // (B,H,DH,S)  (transposed!)
__device__ float g_ctx[(size_t)B_ * SEQ_ * D_];
__device__ float g_scores[(size_t)B_ * H_ * SEQ_ * SEQ_];
__device__ float g_ff[(size_t)B_ * SEQ_ * DFF_];

__device__ __forceinline__ float gelu_exact(float x) {
    return 0.5f * x * (1.0f + erff(x * 0.70710678118654752f));
}

// ---------------- generic tiled SGEMM: C = A(MxK) * B(NxK)^T, mode epilogues -
// MODE 1: QK scatter  -> out[(b*H+h)*S+s][dh] = v + bias[n]
// MODE 2: V transposed-> out[(b*H+h)*DH+dh][s] = v + bias[n]
// MODE 3: scores      -> out[z][m][n] = mask ? -1e9 : v*scale   (batched via z)
// MODE 4: ctx         -> out[(b*S+m)][h*DH+n] = v               (batched via z)
// MODE 5: bias+residual row-major
// MODE 6: gelu(bias) row-major
// MODE 7: embed scatter with per-token additive table
#define BM 128
#define BN 128
#define BK 16

template <int MODE>
__global__ __launch_bounds__(256) void gemm_k(
    const float* __restrict__ A, const float* __restrict__ Bm,
    float* __restrict__ C, int M, int N, int K,
    long sAz, long sBz,
    const float* __restrict__ bias,
    const float* __restrict__ res,
    const float* __restrict__ rowadd,
    float scale, const int* __restrict__ mask)
{
    __shared__ float As[BK][BM];
    __shared__ float Bs[BK][BN];

    const int tid = threadIdx.x;
    const int tx = tid & 15;           // 16 col groups
    const int ty = tid >> 4;           // 16 row groups
    const int row0 = blockIdx.y * BM;
    const int col0 = blockIdx.x * BN;

    A += (long)blockIdx.z * sAz;
    Bm += (long)blockIdx.z * sBz;

    const int lr = tid >> 2;           // 0..63
    const int lc = (tid & 3) * 4;      // 0,4,8,12

    float acc[8][8];
#pragma unroll
    for (int i = 0; i < 8; i++)
#pragma unroll
        for (int j = 0; j < 8; j++) acc[i][j] = 0.f;

    for (int k0 = 0; k0 < K; k0 += BK) {
#pragma unroll
        for (int half = 0; half < 2; half++) {
            int r = lr + half * 64;
            float4 va = make_float4(0.f, 0.f, 0.f, 0.f);
            if (row0 + r < M)
                va = *(const float4*)(A + (long)(row0 + r) * K + k0 + lc);
            As[lc + 0][r] = va.x; As[lc + 1][r] = va.y;
            As[lc + 2][r] = va.z; As[lc + 3][r] = va.w;

            float4 vb = make_float4(0.f, 0.f, 0.f, 0.f);
            if (col0 + r < N)
                vb = *(const float4*)(Bm + (long)(col0 + r) * K + k0 + lc);
            Bs[lc + 0][r] = vb.x; Bs[lc + 1][r] = vb.y;
            Bs[lc + 2][r] = vb.z; Bs[lc + 3][r] = vb.w;
        }
        __syncthreads();

#pragma unroll
        for (int k = 0; k < BK; k++) {
            float a[8], b[8];
#pragma unroll
            for (int i = 0; i < 8; i++) a[i] = As[k][ty * 8 + i];
#pragma unroll
            for (int j = 0; j < 8; j++) b[j] = Bs[k][tx * 8 + j];
#pragma unroll
            for (int i = 0; i < 8; i++)
#pragma unroll
                for (int j = 0; j < 8; j++) acc[i][j] += a[i] * b[j];
        }
        __syncthreads();
    }

#pragma unroll
    for (int i = 0; i < 8; i++) {
        int m = row0 + ty * 8 + i;
        if (m >= M) continue;
#pragma unroll
        for (int j = 0; j < 8; j++) {
            int n = col0 + tx * 8 + j;
            if (n >= N) continue;
            float vl = acc[i][j];
            if constexpr (MODE == 1) {
                int b = m / SEQ_, s = m - b * SEQ_;
                int h = n >> 6, dh = n & 63;
                C[(((long)b * H_ + h) * SEQ_ + s) * DH_ + dh] = vl + bias[n];
            } else if constexpr (MODE == 2) {
                int b = m / SEQ_, s = m - b * SEQ_;
                int h = n >> 6, dh = n & 63;
                C[(((long)b * H_ + h) * DH_ + dh) * SEQ_ + s] = vl + bias[n];
            } else if constexpr (MODE == 3) {
                int z = blockIdx.z;
                int b = z >> 3;
                bool pad = (mask[b * SEQ_ + n] == 0);
                C[(long)z * SEQ_ * SEQ_ + (long)m * SEQ_ + n] =
                    pad ? -1e9f : vl * scale;
            } else if constexpr (MODE == 4) {
                int z = blockIdx.z;
                int b = z >> 3, h = z & 7;
                C[((long)(b * SEQ_ + m)) * D_ + h * DH_ + n] = vl;
            } else if constexpr (MODE == 5) {
                long idx = (long)m * N + n;
                C[idx] = vl + bias[n] + res[idx];
            } else if constexpr (MODE == 6) {
                C[(long)m * N + n] = gelu_exact(vl + bias[n]);
            } else if constexpr (MODE == 7) {
                int b = m / NTOK_, p = m - b * NTOK_;
                C[((long)(b * SEQ_ + 1 + p)) * D_ + n] = vl + rowadd[(long)p * D_ + n];
            }
        }
    }
}

// ---------------- feature transpose (B,CIN,HW) -> rows of g_A (tok, CIN) ----
__global__ void transpose_feat_k(const float* __restrict__ feat,
                                 float* __restrict__ Aout,
                                 int HW, int tokoff)
{
    __shared__ float tile[32][33];
    const int b = blockIdx.z;
    const int hw0 = blockIdx.x * 32;
    const int c0 = blockIdx.y * 32;
    const int tx = threadIdx.x, ty = threadIdx.y;  // 32 x 8

    const float* fb = feat + ((long)b * CIN_ + c0) * HW;
#pragma unroll
    for (int i = ty; i < 32; i += 8) {
        int hw = hw0 + tx;
        tile[i][tx] = (hw < HW) ? fb[(long)i * HW + hw] : 0.f;
    }
    __syncthreads();
#pragma unroll
    for (int i = ty; i < 32; i += 8) {
        int hw = hw0 + i;
        if (hw < HW)
            Aout[((long)(b * NTOK_ + tokoff + hw)) * CIN_ + c0 + tx] = tile[tx][i];
    }
}

// ---------------- per-token additive vector: conv_b + chan_emb + pos_emb ----
__global__ void addvec_k(const float* __restrict__ conv_b,
                         const float* __restrict__ org_emb,
                         const float* __restrict__ r1_emb,
                         const float* __restrict__ r2_emb,
                         const float* __restrict__ pos_emb,
                         float* __restrict__ addv)
{
    int p = blockIdx.x;
    int d = threadIdx.x;
    int ti, tj;
    const float* emb;
    if (p < 768) {
        int h = p / 32, w = p - h * 32;
        ti = h * 10 / 24; tj = w * 10 / 32; emb = org_emb;
    } else if (p < 876) {
        int pp = p - 768;
        int h = pp / 12, w = pp - h * 12;
        ti = h * 10 / 9; tj = w * 10 / 12; emb = r1_emb;
    } else {
        int pp = p - 876;
        int h = pp / 7, w = pp - h * 7;
        ti = h * 10 / 5; tj = w * 10 / 7; emb = r2_emb;
    }
    addv[(long)p * D_ + d] = conv_b[d] + emb[d] + pos_emb[((long)ti * 10 + tj) * D_ + d];
}

__global__ void cls_k(const float* __restrict__ cls_token, float* __restrict__ x)
{
    int b = blockIdx.x, d = threadIdx.x;
    x[((long)b * SEQ_) * D_ + d] = cls_token[d];
}

// ---------------- softmax over one score row ---------------------------------
__global__ void softmax_k(float* __restrict__ sc)
{
    long row = blockIdx.x;
    float* r = sc + row * (long)SEQ_;
    int tid = threadIdx.x;
    __shared__ float sm[256];

    float mx = -1e30f;
    for (int i = tid; i < SEQ_; i += 256) mx = fmaxf(mx, r[i]);
    sm[tid] = mx; __syncthreads();
    for (int s = 128; s > 0; s >>= 1) {
        if (tid < s) sm[tid] = fmaxf(sm[tid], sm[tid + s]);
        __syncthreads();
    }
    mx = sm[0]; __syncthreads();

    float sum = 0.f;
    for (int i = tid; i < SEQ_; i += 256) {
        float e = expf(r[i] - mx);
        r[i] = e;
        sum += e;
    }
    sm[tid] = sum; __syncthreads();
    for (int s = 128; s > 0; s >>= 1) {
        if (tid < s) sm[tid] += sm[tid + s];
        __syncthreads();
    }
    float inv = 1.f / sm[0];
    for (int i = tid; i < SEQ_; i += 256) r[i] *= inv;
}

// ---------------- layernorm over D=512 ---------------------------------------
__global__ void ln_k(const float* __restrict__ in, float* __restrict__ out,
                     const float* __restrict__ g, const float* __restrict__ bb)
{
    long t = blockIdx.x;
    const float* x = in + t * D_;
    float* o = out + t * D_;
    int tid = threadIdx.x;
    __shared__ float sm[256];

    float s = 0.f;
    for (int i = tid; i < D_; i += 256) s += x[i];
    sm[tid] = s; __syncthreads();
    for (int k = 128; k > 0; k >>= 1) {
        if (tid < k) sm[tid] += sm[tid + k];
        __syncthreads();
    }
    float mean = sm[0] * (1.f / D_); __syncthreads();

    float v = 0.f;
    for (int i = tid; i < D_; i += 256) {
        float d = x[i] - mean;
        v += d * d;
    }
    sm[tid] = v; __syncthreads();
    for (int k = 128; k > 0; k >>= 1) {
        if (tid < k) sm[tid] += sm[tid + k];
        __syncthreads();
    }
    float rstd = rsqrtf(sm[0] * (1.f / D_) + 1e-6f);
    for (int i = tid; i < D_; i += 256)
        o[i] = (x[i] - mean) * rstd * g[i] + bb[i];
}

// ---------------- MLP head on cls token --------------------------------------
__global__ void head_k(const float* __restrict__ x,
                       const float* __restrict__ w1,
                       const float* __restrict__ w2,
                       float* __restrict__ out)
{
    int b = blockIdx.x;
    int tid = threadIdx.x;
    __shared__ float cls[D_];
    __shared__ float red[256];
    for (int i = tid; i < D_; i += 256)
        cls[i] = x[((long)b * SEQ_) * D_ + i];
    __syncthreads();

    float partial = 0.f;
    for (int j = tid; j < DMLP_; j += 256) {
        const float* w = w1 + (long)j * D_;
        float s = 0.f;
#pragma unroll 8
        for (int k = 0; k < D_; k++) s += cls[k] * w[k];
        partial += gelu_exact(s) * w2[j];
    }
    red[tid] = partial; __syncthreads();
    for (int k = 128; k > 0; k >>= 1) {
        if (tid < k) red[tid] += red[tid + k];
        __syncthreads();
    }
    if (tid == 0) out[b] = red[0];
}

// =============================================================================
extern "C" void kernel_launch(void* const* d_in, const int* in_sizes, int n_in,
                              void* d_out, int out_size)
{
    const float* feat_org = (const float*)d_in[0];
    const float* feat_r1  = (const float*)d_in[1];
    const float* feat_r2  = (const float*)d_in[2];
    const float* conv_w   = (const float*)d_in[3];
    const float* conv_b   = (const float*)d_in[4];
    const float* org_emb  = (const float*)d_in[5];
    const float* r1_emb   = (const float*)d_in[6];
    const float* r2_emb   = (const float*)d_in[7];
    const float* pos_emb  = (const float*)d_in[8];
    const float* cls_tok  = (const float*)d_in[9];
    const float* Wq = (const float*)d_in[10];
    const float* bq = (const float*)d_in[11];
    const float* Wk = (const float*)d_in[12];
    const float* bk = (const float*)d_in[13];
    const float* Wv = (const float*)d_in[14];
    const float* bv = (const float*)d_in[15];
    const float* Wo = (const float*)d_in[16];
    const float* bo = (const float*)d_in[17];
    const float* ln1g = (const float*)d_in[18];
    const float* ln1b = (const float*)d_in[19];
    const float* w1 = (const float*)d_in[20];
    const float* b1 = (const float*)d_in[21];
    const float* w2 = (const float*)d_in[22];
    const float* b2 = (const float*)d_in[23];
    const float* ln2g = (const float*)d_in[24];
    const float* ln2b = (const float*)d_in[25];
    const float* pw1 = (const float*)d_in[26];
    const float* pw2 = (const float*)d_in[27];
    const int*   mask = (const int*)d_in[28];
    float* out = (float*)d_out;

    float *A, *addv, *x, *tmp, *q, *k, *v, *ctx, *sc, *ff;
    cudaGetSymbolAddress((void**)&A, g_A);
    cudaGetSymbolAddress((void**)&addv, g_add);
    cudaGetSymbolAddress((void**)&x, g_x);
    cudaGetSymbolAddress((void**)&tmp, g_tmp);
    cudaGetSymbolAddress((void**)&q, g_q);
    cudaGetSymbolAddress((void**)&k, g_k);
    cudaGetSymbolAddress((void**)&v, g_v);
    cudaGetSymbolAddress((void**)&ctx, g_ctx);
    cudaGetSymbolAddress((void**)&sc, g_scores);
    cudaGetSymbolAddress((void**)&ff, g_ff);

    dim3 tb(32, 8);
    transpose_feat_k<<<dim3(24, CIN_ / 32, B_), tb>>>(feat_org, A, 768, 0);
    transpose_feat_k<<<dim3(4,  CIN_ / 32, B_), tb>>>(feat_r1,  A, 108, 768);
    transpose_feat_k<<<dim3(2,  CIN_ / 32, B_), tb>>>(feat_r2,  A, 35,  876);
    addvec_k<<<NTOK_, D_>>>(conv_b, org_emb, r1_emb, r2_emb, pos_emb, addv);

    // patch embed: x[b, 1+p, :] = A @ conv_w^T + addv
    gemm_k<7><<<dim3(4, 57, 1), 256>>>(A, conv_w, x, B_ * NTOK_, D_, CIN_,
                                       0, 0, nullptr, nullptr, addv, 0.f, nullptr);
    cls_k<<<B_, D_>>>(cls_tok, x);

    const float scale = 0.125f;  // 1/sqrt(64)
    for (int i = 0; i < L_; i++) {
        const float* wq = Wq + (long)i * D_ * D_;
        const float* wk = Wk + (long)i * D_ * D_;
        const float* wv = Wv + (long)i * D_ * D_;
        const float* wo = Wo + (long)i * D_ * D_;

        gemm_k<1><<<dim3(4, 57, 1), 256>>>(x, wq, q, B_ * SEQ_, D_, D_,
                                           0, 0, bq + i * D_, nullptr, nullptr, 0.f, nullptr);
        gemm_k<1><<<dim3(4, 57, 1), 256>>>(x, wk, k, B_ * SEQ_, D_, D_,
                                           0, 0, bk + i * D_, nullptr, nullptr, 0.f, nullptr);
        gemm_k<2><<<dim3(4, 57, 1), 256>>>(x, wv, v, B_ * SEQ_, D_, D_,
                                           0, 0, bv + i * D_, nullptr, nullptr, 0.f, nullptr);

        gemm_k<3><<<dim3(8, 8, B_ * H_), 256>>>(q, k, sc, SEQ_, SEQ_, DH_,
                                                (long)SEQ_ * DH_, (long)SEQ_ * DH_,
                                                nullptr, nullptr, nullptr, scale, mask);
        softmax_k<<<B_ * H_ * SEQ_, 256>>>(sc);
        gemm_k<4><<<dim3(1, 8, B_ * H_), 256>>>(sc, v, ctx, SEQ_, DH_, SEQ_,
                                                (long)SEQ_ * SEQ_, (long)DH_ * SEQ_,
                                                nullptr, nullptr, nullptr, 0.f, nullptr);

        gemm_k<5><<<dim3(4, 57, 1), 256>>>(ctx, wo, tmp, B_ * SEQ_, D_, D_,
                                           0, 0, bo + i * D_, x, nullptr, 0.f, nullptr);
        ln_k<<<B_ * SEQ_, 256>>>(tmp, x, ln1g + i * D_, ln1b + i * D_);

        gemm_k<6><<<dim3(16, 57, 1), 256>>>(x, w1 + (long)i * DFF_ * D_, ff,
                                            B_ * SEQ_, DFF_, D_,
                                            0, 0, b1 + i * DFF_, nullptr, nullptr, 0.f, nullptr);
        gemm_k<5><<<dim3(4, 57, 1), 256>>>(ff, w2 + (long)i * D_ * DFF_, tmp,
                                           B_ * SEQ_, D_, DFF_,
                                           0, 0, b2 + i * D_, x, nullptr, 0.f, nullptr);
        ln_k<<<B_ * SEQ_, 256>>>(tmp, x, ln2g + i * D_, ln2b + i * D_);
    }

    head_k<<<B_, 256>>>(x, pw1, pw2, out);
}

// round 2
// speedup vs baseline: 2.2148x; 2.2148x over previous
#include <cuda_runtime.h>
#include <math.h>
#include <stdint.h>

#define B_    8
#define D_    512
#define H_    8
#define DH_   64
#define L_    6
#define DFF_  2048
#define CIN_  2048
#define SEQ_  912
#define NTOK_ 911
#define DMLP_ 1024

// ---------------- scratch (static device globals; allocation-free) ----------
__device__ __align__(16) float g_A[(size_t)B_ * NTOK_ * CIN_];
__device__ __align__(16) float g_add[(size_t)NTOK_ * D_];
__device__ __align__(16) float g_x[(size_t)B_ * SEQ_ * D_];
__device__ __align__(16) float g_tmp[(size_t)B_ * SEQ_ * D_];
__device__ __align__(16) float g_q[(size_t)B_ * SEQ_ * D_];    // (B,H,S,DH)
__device__ __align__(16) float g_k[(size_t)B_ * SEQ_ * D_];    // (B,H,S,DH)
__device__ __align__(16) float g_v[(size_t)B_ * SEQ_ * D_];    // (B,H,DH,S)
__device__ __align__(16) float g_ctx[(size_t)B_ * SEQ_ * D_];
__device__ __align__(16) float g_scores[(size_t)B_ * H_ * SEQ_ * SEQ_];
__device__ __align__(16) float g_ff[(size_t)B_ * SEQ_ * DFF_];

__device__ __forceinline__ float gelu_exact(float x) {
    return 0.5f * x * (1.0f + erff(x * 0.70710678118654752f));
}

__device__ __forceinline__ float f2tf32(float x) {
    uint32_t r;
    asm("cvt.rna.tf32.f32 %0, %1;" : "=r"(r) : "f"(x));
    return __uint_as_float(r);
}

__device__ __forceinline__ void mma_tf32(float c[4], const uint32_t a[4],
                                         const uint32_t b[2]) {
    asm volatile(
        "mma.sync.aligned.m16n8k8.row.col.f32.tf32.tf32.f32 "
        "{%0,%1,%2,%3}, {%4,%5,%6,%7}, {%8,%9}, {%0,%1,%2,%3};"
        : "+f"(c[0]), "+f"(c[1]), "+f"(c[2]), "+f"(c[3])
        : "r"(a[0]), "r"(a[1]), "r"(a[2]), "r"(a[3]), "r"(b[0]), "r"(b[1]));
}

// ---------------- TF32 tensor-core GEMM: C = A(MxK) * B(NxK)^T --------------
// MODE 1: QK scatter (q/k layout B,H,S,DH), +bias
// MODE 2: V transposed scatter (B,H,DH,S), +bias
// MODE 3: scores (batched z), mask + scale
// MODE 4: ctx (batched z) -> (B,S,D) gather
// MODE 5: bias + residual, row-major
// MODE 6: gelu(bias), row-major
// MODE 7: embed scatter with per-token additive table
template <int BN, int MODE>
__global__ __launch_bounds__(256) void gemm_tc(
    const float* __restrict__ A, const float* __restrict__ Bm,
    float* __restrict__ C, int M, int N, int K,
    long sAz, long sBz,
    const float* __restrict__ bias,
    const float* __restrict__ res,
    const float* __restrict__ rowadd,
    float scale, const int* __restrict__ mask)
{
    constexpr int BM = 128;
    constexpr int BK = 16;
    constexpr int LDS_ = BK + 4;       // stride 20 floats -> conflict-free frags
    constexpr int WN = BN / 4;         // warp tile N (32 or 16)
    constexpr int MT = 4;              // 64/16 m-tiles per warp
    constexpr int NT = WN / 8;         // n-tiles per warp (4 or 2)
    constexpr int AR = BM / 64;        // float4 loads per thread (A)
    constexpr int BR = BN / 64;        // float4 loads per thread (B)

    __shared__ float As[2][BM][LDS_];
    __shared__ float Bs[2][BN][LDS_];

    const int tid  = threadIdx.x;
    const int lane = tid & 31;
    const int wid  = tid >> 5;
    const int wm   = wid & 1;          // warp row (0..1)
    const int wn   = wid >> 1;         // warp col (0..3)
    const int row0 = blockIdx.y * BM;
    const int col0 = blockIdx.x * BN;

    A  += (long)blockIdx.z * sAz;
    Bm += (long)blockIdx.z * sBz;

    const int lr = tid >> 2;           // 0..63
    const int lc = (tid & 3) * 4;      // 0,4,8,12

    float acc[MT][NT][4];
#pragma unroll
    for (int i = 0; i < MT; i++)
#pragma unroll
        for (int j = 0; j < NT; j++)
#pragma unroll
            for (int e = 0; e < 4; e++) acc[i][j][e] = 0.f;

    float4 pa[AR], pb[BR];

    auto ldg_tiles = [&](int k0) {
#pragma unroll
        for (int i = 0; i < AR; i++) {
            int r = lr + i * 64;
            pa[i] = make_float4(0.f, 0.f, 0.f, 0.f);
            if (row0 + r < M)
                pa[i] = *(const float4*)(A + (long)(row0 + r) * K + k0 + lc);
        }
#pragma unroll
        for (int i = 0; i < BR; i++) {
            int r = lr + i * 64;
            pb[i] = make_float4(0.f, 0.f, 0.f, 0.f);
            if (col0 + r < N)
                pb[i] = *(const float4*)(Bm + (long)(col0 + r) * K + k0 + lc);
        }
    };
    auto sts_tiles = [&](int buf) {
#pragma unroll
        for (int i = 0; i < AR; i++) {
            int r = lr + i * 64;
            As[buf][r][lc + 0] = f2tf32(pa[i].x);
            As[buf][r][lc + 1] = f2tf32(pa[i].y);
            As[buf][r][lc + 2] = f2tf32(pa[i].z);
            As[buf][r][lc + 3] = f2tf32(pa[i].w);
        }
#pragma unroll
        for (int i = 0; i < BR; i++) {
            int r = lr + i * 64;
            Bs[buf][r][lc + 0] = f2tf32(pb[i].x);
            Bs[buf][r][lc + 1] = f2tf32(pb[i].y);
            Bs[buf][r][lc + 2] = f2tf32(pb[i].z);
            Bs[buf][r][lc + 3] = f2tf32(pb[i].w);
        }
    };

    const int kIters = K / BK;
    ldg_tiles(0);
    sts_tiles(0);
    __syncthreads();

    for (int it = 0; it < kIters; ++it) {
        const int buf = it & 1;
        if (it + 1 < kIters) ldg_tiles((it + 1) * BK);

#pragma unroll
        for (int kk = 0; kk < 2; kk++) {
            const int kb = kk * 8 + (lane & 3);
            uint32_t af[MT][4], bf[NT][2];
#pragma unroll
            for (int im = 0; im < MT; im++) {
                int m = wm * 64 + im * 16 + (lane >> 2);
                af[im][0] = __float_as_uint(As[buf][m][kb]);
                af[im][1] = __float_as_uint(As[buf][m + 8][kb]);
                af[im][2] = __float_as_uint(As[buf][m][kb + 4]);
                af[im][3] = __float_as_uint(As[buf][m + 8][kb + 4]);
            }
#pragma unroll
            for (int jn = 0; jn < NT; jn++) {
                int n = wn * WN + jn * 8 + (lane >> 2);
                bf[jn][0] = __float_as_uint(Bs[buf][n][kb]);
                bf[jn][1] = __float_as_uint(Bs[buf][n][kb + 4]);
            }
#pragma unroll
            for (int im = 0; im < MT; im++)
#pragma unroll
                for (int jn = 0; jn < NT; jn++)
                    mma_tf32(acc[im][jn], af[im], bf[jn]);
        }

        if (it + 1 < kIters) {
            sts_tiles(buf ^ 1);
            __syncthreads();
        }
    }

    // ---------------- epilogue ----------------
#pragma unroll
    for (int im = 0; im < MT; im++) {
#pragma unroll
        for (int jn = 0; jn < NT; jn++) {
#pragma unroll
            for (int e = 0; e < 4; e++) {
                int m = row0 + wm * 64 + im * 16 + (lane >> 2) + ((e >> 1) * 8);
                int n = col0 + wn * WN + jn * 8 + (lane & 3) * 2 + (e & 1);
                if (m >= M || n >= N) continue;
                float vl = acc[im][jn][e];
                if constexpr (MODE == 1) {
                    int b = m / SEQ_, s = m - b * SEQ_;
                    int h = n >> 6, dh = n & 63;
                    C[(((long)b * H_ + h) * SEQ_ + s) * DH_ + dh] = vl + bias[n];
                } else if constexpr (MODE == 2) {
                    int b = m / SEQ_, s = m - b * SEQ_;
                    int h = n >> 6, dh = n & 63;
                    C[(((long)b * H_ + h) * DH_ + dh) * SEQ_ + s] = vl + bias[n];
                } else if constexpr (MODE == 3) {
                    int z = blockIdx.z;
                    int b = z >> 3;
                    bool pad = (mask[b * SEQ_ + n] == 0);
                    C[(long)z * SEQ_ * SEQ_ + (long)m * SEQ_ + n] =
                        pad ? -1e9f : vl * scale;
                } else if constexpr (MODE == 4) {
                    int z = blockIdx.z;
                    int b = z >> 3, h = z & 7;
                    C[((long)(b * SEQ_ + m)) * D_ + h * DH_ + n] = vl;
                } else if constexpr (MODE == 5) {
                    long idx = (long)m * N + n;
                    C[idx] = vl + bias[n] + res[idx];
                } else if constexpr (MODE == 6) {
                    C[(long)m * N + n] = gelu_exact(vl + bias[n]);
                } else if constexpr (MODE == 7) {
                    int b = m / NTOK_, p = m - b * NTOK_;
                    C[((long)(b * SEQ_ + 1 + p)) * D_ + n] =
                        vl + rowadd[(long)p * D_ + n];
                }
            }
        }
    }
}

// ---------------- feature transpose (B,CIN,HW) -> rows of g_A (tok, CIN) ----
__global__ void transpose_feat_k(const float* __restrict__ feat,
                                 float* __restrict__ Aout,
                                 int HW, int tokoff)
{
    __shared__ float tile[32][33];
    const int b = blockIdx.z;
    const int hw0 = blockIdx.x * 32;
    const int c0 = blockIdx.y * 32;
    const int tx = threadIdx.x, ty = threadIdx.y;

    const float* fb = feat + ((long)b * CIN_ + c0) * HW;
#pragma unroll
    for (int i = ty; i < 32; i += 8) {
        int hw = hw0 + tx;
        tile[i][tx] = (hw < HW) ? fb[(long)i * HW + hw] : 0.f;
    }
    __syncthreads();
#pragma unroll
    for (int i = ty; i < 32; i += 8) {
        int hw = hw0 + i;
        if (hw < HW)
            Aout[((long)(b * NTOK_ + tokoff + hw)) * CIN_ + c0 + tx] = tile[tx][i];
    }
}

__global__ void addvec_k(const float* __restrict__ conv_b,
                         const float* __restrict__ org_emb,
                         const float* __restrict__ r1_emb,
                         const float* __restrict__ r2_emb,
                         const float* __restrict__ pos_emb,
                         float* __restrict__ addv)
{
    int p = blockIdx.x;
    int d = threadIdx.x;
    int ti, tj;
    const float* emb;
    if (p < 768) {
        int h = p / 32, w = p - h * 32;
        ti = h * 10 / 24; tj = w * 10 / 32; emb = org_emb;
    } else if (p < 876) {
        int pp = p - 768;
        int h = pp / 12, w = pp - h * 12;
        ti = h * 10 / 9; tj = w * 10 / 12; emb = r1_emb;
    } else {
        int pp = p - 876;
        int h = pp / 7, w = pp - h * 7;
        ti = h * 10 / 5; tj = w * 10 / 7; emb = r2_emb;
    }
    addv[(long)p * D_ + d] = conv_b[d] + emb[d] + pos_emb[((long)ti * 10 + tj) * D_ + d];
}

__global__ void cls_k(const float* __restrict__ cls_token, float* __restrict__ x)
{
    int b = blockIdx.x, d = threadIdx.x;
    x[((long)b * SEQ_) * D_ + d] = cls_token[d];
}

// ---------------- softmax over one score row ---------------------------------
__global__ void softmax_k(float* __restrict__ sc)
{
    long row = blockIdx.x;
    float* r = sc + row * (long)SEQ_;
    int tid = threadIdx.x;
    __shared__ float sm[256];

    float mx = -1e30f;
    for (int i = tid; i < SEQ_; i += 256) mx = fmaxf(mx, r[i]);
    sm[tid] = mx; __syncthreads();
    for (int s = 128; s > 0; s >>= 1) {
        if (tid < s) sm[tid] = fmaxf(sm[tid], sm[tid + s]);
        __syncthreads();
    }
    mx = sm[0]; __syncthreads();

    float sum = 0.f;
    for (int i = tid; i < SEQ_; i += 256) {
        float e = expf(r[i] - mx);
        r[i] = e;
        sum += e;
    }
    sm[tid] = sum; __syncthreads();
    for (int s = 128; s > 0; s >>= 1) {
        if (tid < s) sm[tid] += sm[tid + s];
        __syncthreads();
    }
    float inv = 1.f / sm[0];
    for (int i = tid; i < SEQ_; i += 256) r[i] *= inv;
}

// ---------------- layernorm over D=512 ---------------------------------------
__global__ void ln_k(const float* __restrict__ in, float* __restrict__ out,
                     const float* __restrict__ g, const float* __restrict__ bb)
{
    long t = blockIdx.x;
    const float* x = in + t * D_;
    float* o = out + t * D_;
    int tid = threadIdx.x;
    __shared__ float sm[256];

    float s = 0.f;
    for (int i = tid; i < D_; i += 256) s += x[i];
    sm[tid] = s; __syncthreads();
    for (int k = 128; k > 0; k >>= 1) {
        if (tid < k) sm[tid] += sm[tid + k];
        __syncthreads();
    }
    float mean = sm[0] * (1.f / D_); __syncthreads();

    float v = 0.f;
    for (int i = tid; i < D_; i += 256) {
        float d = x[i] - mean;
        v += d * d;
    }
    sm[tid] = v; __syncthreads();
    for (int k = 128; k > 0; k >>= 1) {
        if (tid < k) sm[tid] += sm[tid + k];
        __syncthreads();
    }
    float rstd = rsqrtf(sm[0] * (1.f / D_) + 1e-6f);
    for (int i = tid; i < D_; i += 256)
        o[i] = (x[i] - mean) * rstd * g[i] + bb[i];
}

// ---------------- MLP head on cls token --------------------------------------
__global__ void head_k(const float* __restrict__ x,
                       const float* __restrict__ w1,
                       const float* __restrict__ w2,
                       float* __restrict__ out)
{
    int b = blockIdx.x;
    int tid = threadIdx.x;
    __shared__ float cls[D_];
    __shared__ float red[256];
    for (int i = tid; i < D_; i += 256)
        cls[i] = x[((long)b * SEQ_) * D_ + i];
    __syncthreads();

    float partial = 0.f;
    for (int j = tid; j < DMLP_; j += 256) {
        const float* w = w1 + (long)j * D_;
        float s = 0.f;
#pragma unroll 8
        for (int k = 0; k < D_; k++) s += cls[k] * w[k];
        partial += gelu_exact(s) * w2[j];
    }
    red[tid] = partial; __syncthreads();
    for (int k = 128; k > 0; k >>= 1) {
        if (tid < k) red[tid] += red[tid + k];
        __syncthreads();
    }
    if (tid == 0) out[b] = red[0];
}

// =============================================================================
extern "C" void kernel_launch(void* const* d_in, const int* in_sizes, int n_in,
                              void* d_out, int out_size)
{
    const float* feat_org = (const float*)d_in[0];
    const float* feat_r1  = (const float*)d_in[1];
    const float* feat_r2  = (const float*)d_in[2];
    const float* conv_w   = (const float*)d_in[3];
    const float* conv_b   = (const float*)d_in[4];
    const float* org_emb  = (const float*)d_in[5];
    const float* r1_emb   = (const float*)d_in[6];
    const float* r2_emb   = (const float*)d_in[7];
    const float* pos_emb  = (const float*)d_in[8];
    const float* cls_tok  = (const float*)d_in[9];
    const float* Wq = (const float*)d_in[10];
    const float* bq = (const float*)d_in[11];
    const float* Wk = (const float*)d_in[12];
    const float* bk = (const float*)d_in[13];
    const float* Wv = (const float*)d_in[14];
    const float* bv = (const float*)d_in[15];
    const float* Wo = (const float*)d_in[16];
    const float* bo = (const float*)d_in[17];
    const float* ln1g = (const float*)d_in[18];
    const float* ln1b = (const float*)d_in[19];
    const float* w1 = (const float*)d_in[20];
    const float* b1 = (const float*)d_in[21];
    const float* w2 = (const float*)d_in[22];
    const float* b2 = (const float*)d_in[23];
    const float* ln2g = (const float*)d_in[24];
    const float* ln2b = (const float*)d_in[25];
    const float* pw1 = (const float*)d_in[26];
    const float* pw2 = (const float*)d_in[27];
    const int*   mask = (const int*)d_in[28];
    float* out = (float*)d_out;

    float *A, *addv, *x, *tmp, *q, *k, *v, *ctx, *sc, *ff;
    cudaGetSymbolAddress((void**)&A, g_A);
    cudaGetSymbolAddress((void**)&addv, g_add);
    cudaGetSymbolAddress((void**)&x, g_x);
    cudaGetSymbolAddress((void**)&tmp, g_tmp);
    cudaGetSymbolAddress((void**)&q, g_q);
    cudaGetSymbolAddress((void**)&k, g_k);
    cudaGetSymbolAddress((void**)&v, g_v);
    cudaGetSymbolAddress((void**)&ctx, g_ctx);
    cudaGetSymbolAddress((void**)&sc, g_scores);
    cudaGetSymbolAddress((void**)&ff, g_ff);

    dim3 tb(32, 8);
    transpose_feat_k<<<dim3(24, CIN_ / 32, B_), tb>>>(feat_org, A, 768, 0);
    transpose_feat_k<<<dim3(4,  CIN_ / 32, B_), tb>>>(feat_r1,  A, 108, 768);
    transpose_feat_k<<<dim3(2,  CIN_ / 32, B_), tb>>>(feat_r2,  A, 35,  876);
    addvec_k<<<NTOK_, D_>>>(conv_b, org_emb, r1_emb, r2_emb, pos_emb, addv);

    // patch embed: x[b, 1+p, :] = A @ conv_w^T + addv
    gemm_tc<128, 7><<<dim3(4, 57, 1), 256>>>(A, conv_w, x, B_ * NTOK_, D_, CIN_,
                                             0, 0, nullptr, nullptr, addv, 0.f, nullptr);
    cls_k<<<B_, D_>>>(cls_tok, x);

    const float scale = 0.125f;  // 1/sqrt(64)
    for (int i = 0; i < L_; i++) {
        const float* wq = Wq + (long)i * D_ * D_;
        const float* wk = Wk + (long)i * D_ * D_;
        const float* wv = Wv + (long)i * D_ * D_;
        const float* wo = Wo + (long)i * D_ * D_;

        gemm_tc<128, 1><<<dim3(4, 57, 1), 256>>>(x, wq, q, B_ * SEQ_, D_, D_,
                                                 0, 0, bq + i * D_, nullptr, nullptr, 0.f, nullptr);
        gemm_tc<128, 1><<<dim3(4, 57, 1), 256>>>(x, wk, k, B_ * SEQ_, D_, D_,
                                                 0, 0, bk + i * D_, nullptr, nullptr, 0.f, nullptr);
        gemm_tc<128, 2><<<dim3(4, 57, 1), 256>>>(x, wv, v, B_ * SEQ_, D_, D_,
                                                 0, 0, bv + i * D_, nullptr, nullptr, 0.f, nullptr);

        gemm_tc<128, 3><<<dim3(8, 8, B_ * H_), 256>>>(q, k, sc, SEQ_, SEQ_, DH_,
                                                      (long)SEQ_ * DH_, (long)SEQ_ * DH_,
                                                      nullptr, nullptr, nullptr, scale, mask);
        softmax_k<<<B_ * H_ * SEQ_, 256>>>(sc);
        gemm_tc<64, 4><<<dim3(1, 8, B_ * H_), 256>>>(sc, v, ctx, SEQ_, DH_, SEQ_,
                                                     (long)SEQ_ * SEQ_, (long)DH_ * SEQ_,
                                                     nullptr, nullptr, nullptr, 0.f, nullptr);

        gemm_tc<128, 5><<<dim3(4, 57, 1), 256>>>(ctx, wo, tmp, B_ * SEQ_, D_, D_,
                                                 0, 0, bo + i * D_, x, nullptr, 0.f, nullptr);
        ln_k<<<B_ * SEQ_, 256>>>(tmp, x, ln1g + i * D_, ln1b + i * D_);

        gemm_tc<128, 6><<<dim3(16, 57, 1), 256>>>(x, w1 + (long)i * DFF_ * D_, ff,
                                                  B_ * SEQ_, DFF_, D_,
                                                  0, 0, b1 + i * DFF_, nullptr, nullptr, 0.f, nullptr);
        gemm_tc<128, 5><<<dim3(4, 57, 1), 256>>>(ff, w2 + (long)i * D_ * DFF_, tmp,
                                                 B_ * SEQ_, D_, DFF_,
                                                 0, 0, b2 + i * D_, x, nullptr, 0.f, nullptr);
        ln_k<<<B_ * SEQ_, 256>>>(tmp, x, ln2g + i * D_, ln2b + i * D_);
    }

    head_k<<<B_, 256>>>(x, pw1, pw2, out);
}

// round 3
// speedup vs baseline: 2.3046x; 1.0406x over previous
#include <cuda_runtime.h>
#include <math.h>
#include <stdint.h>

#define B_    8
#define D_    512
#define H_    8
#define DH_   64
#define L_    6
#define DFF_  2048
#define CIN_  2048
#define SEQ_  912
#define NTOK_ 911
#define DMLP_ 1024

// ---------------- scratch (static device globals; allocation-free) ----------
__device__ __align__(16) float g_A[(size_t)B_ * NTOK_ * CIN_];
__device__ __align__(16) float g_add[(size_t)NTOK_ * D_];
__device__ __align__(16) float g_x[(size_t)B_ * SEQ_ * D_];
__device__ __align__(16) float g_tmp[(size_t)B_ * SEQ_ * D_];
__device__ __align__(16) float g_q[(size_t)B_ * SEQ_ * D_];    // (B,H,S,DH)
__device__ __align__(16) float g_k[(size_t)B_ * SEQ_ * D_];    // (B,H,S,DH)
__device__ __align__(16) float g_v[(size_t)B_ * SEQ_ * D_];    // (B,H,S,DH)
__device__ __align__(16) float g_ctx[(size_t)B_ * SEQ_ * D_];
__device__ __align__(16) float g_ff[(size_t)B_ * SEQ_ * DFF_];

__device__ __forceinline__ float gelu_exact(float x) {
    return 0.5f * x * (1.0f + erff(x * 0.70710678118654752f));
}

__device__ __forceinline__ float f2tf32(float x) {
    uint32_t r;
    asm("cvt.rna.tf32.f32 %0, %1;" : "=r"(r) : "f"(x));
    return __uint_as_float(r);
}

__device__ __forceinline__ void mma_tf32(float c[4], const uint32_t a[4],
                                         const uint32_t b[2]) {
    asm volatile(
        "mma.sync.aligned.m16n8k8.row.col.f32.tf32.tf32.f32 "
        "{%0,%1,%2,%3}, {%4,%5,%6,%7}, {%8,%9}, {%0,%1,%2,%3};"
        : "+f"(c[0]), "+f"(c[1]), "+f"(c[2]), "+f"(c[3])
        : "r"(a[0]), "r"(a[1]), "r"(a[2]), "r"(a[3]), "r"(b[0]), "r"(b[1]));
}

// ---------------- TF32 tensor-core GEMM: C = A(MxK) * B(NxK)^T --------------
// MODE 1: scatter (B,H,S,DH), +bias        (q, k, v)
// MODE 5: bias + residual, row-major
// MODE 6: gelu(bias), row-major
// MODE 7: embed scatter with per-token additive table
template <int BN, int MODE>
__global__ __launch_bounds__(256) void gemm_tc(
    const float* __restrict__ A, const float* __restrict__ Bm,
    float* __restrict__ C, int M, int N, int K,
    const float* __restrict__ bias,
    const float* __restrict__ res,
    const float* __restrict__ rowadd)
{
    constexpr int BM = 128;
    constexpr int BK = 16;
    constexpr int LDS_ = BK + 4;
    constexpr int WN = BN / 4;
    constexpr int MT = 4;
    constexpr int NT = WN / 8;
    constexpr int AR = BM / 64;
    constexpr int BR = BN / 64;

    __shared__ float As[2][BM][LDS_];
    __shared__ float Bs[2][BN][LDS_];

    const int tid  = threadIdx.x;
    const int lane = tid & 31;
    const int wid  = tid >> 5;
    const int wm   = wid & 1;
    const int wn   = wid >> 1;
    const int row0 = blockIdx.y * BM;
    const int col0 = blockIdx.x * BN;

    const int lr = tid >> 2;
    const int lc = (tid & 3) * 4;

    float acc[MT][NT][4];
#pragma unroll
    for (int i = 0; i < MT; i++)
#pragma unroll
        for (int j = 0; j < NT; j++)
#pragma unroll
            for (int e = 0; e < 4; e++) acc[i][j][e] = 0.f;

    float4 pa[AR], pb[BR];

    auto ldg_tiles = [&](int k0) {
#pragma unroll
        for (int i = 0; i < AR; i++) {
            int r = lr + i * 64;
            pa[i] = make_float4(0.f, 0.f, 0.f, 0.f);
            if (row0 + r < M)
                pa[i] = *(const float4*)(A + (long)(row0 + r) * K + k0 + lc);
        }
#pragma unroll
        for (int i = 0; i < BR; i++) {
            int r = lr + i * 64;
            pb[i] = make_float4(0.f, 0.f, 0.f, 0.f);
            if (col0 + r < N)
                pb[i] = *(const float4*)(Bm + (long)(col0 + r) * K + k0 + lc);
        }
    };
    auto sts_tiles = [&](int buf) {
#pragma unroll
        for (int i = 0; i < AR; i++) {
            int r = lr + i * 64;
            As[buf][r][lc + 0] = f2tf32(pa[i].x);
            As[buf][r][lc + 1] = f2tf32(pa[i].y);
            As[buf][r][lc + 2] = f2tf32(pa[i].z);
            As[buf][r][lc + 3] = f2tf32(pa[i].w);
        }
#pragma unroll
        for (int i = 0; i < BR; i++) {
            int r = lr + i * 64;
            Bs[buf][r][lc + 0] = f2tf32(pb[i].x);
            Bs[buf][r][lc + 1] = f2tf32(pb[i].y);
            Bs[buf][r][lc + 2] = f2tf32(pb[i].z);
            Bs[buf][r][lc + 3] = f2tf32(pb[i].w);
        }
    };

    const int kIters = K / BK;
    ldg_tiles(0);
    sts_tiles(0);
    __syncthreads();

    for (int it = 0; it < kIters; ++it) {
        const int buf = it & 1;
        if (it + 1 < kIters) ldg_tiles((it + 1) * BK);

#pragma unroll
        for (int kk = 0; kk < 2; kk++) {
            const int kb = kk * 8 + (lane & 3);
            uint32_t af[MT][4], bf[NT][2];
#pragma unroll
            for (int im = 0; im < MT; im++) {
                int m = wm * 64 + im * 16 + (lane >> 2);
                af[im][0] = __float_as_uint(As[buf][m][kb]);
                af[im][1] = __float_as_uint(As[buf][m + 8][kb]);
                af[im][2] = __float_as_uint(As[buf][m][kb + 4]);
                af[im][3] = __float_as_uint(As[buf][m + 8][kb + 4]);
            }
#pragma unroll
            for (int jn = 0; jn < NT; jn++) {
                int n = wn * WN + jn * 8 + (lane >> 2);
                bf[jn][0] = __float_as_uint(Bs[buf][n][kb]);
                bf[jn][1] = __float_as_uint(Bs[buf][n][kb + 4]);
            }
#pragma unroll
            for (int im = 0; im < MT; im++)
#pragma unroll
                for (int jn = 0; jn < NT; jn++)
                    mma_tf32(acc[im][jn], af[im], bf[jn]);
        }

        if (it + 1 < kIters) {
            sts_tiles(buf ^ 1);
            __syncthreads();
        }
    }

#pragma unroll
    for (int im = 0; im < MT; im++) {
#pragma unroll
        for (int jn = 0; jn < NT; jn++) {
#pragma unroll
            for (int e = 0; e < 4; e++) {
                int m = row0 + wm * 64 + im * 16 + (lane >> 2) + ((e >> 1) * 8);
                int n = col0 + wn * WN + jn * 8 + (lane & 3) * 2 + (e & 1);
                if (m >= M || n >= N) continue;
                float vl = acc[im][jn][e];
                if constexpr (MODE == 1) {
                    int b = m / SEQ_, s = m - b * SEQ_;
                    int h = n >> 6, dh = n & 63;
                    C[(((long)b * H_ + h) * SEQ_ + s) * DH_ + dh] = vl + bias[n];
                } else if constexpr (MODE == 5) {
                    long idx = (long)m * N + n;
                    C[idx] = vl + bias[n] + res[idx];
                } else if constexpr (MODE == 6) {
                    C[(long)m * N + n] = gelu_exact(vl + bias[n]);
                } else if constexpr (MODE == 7) {
                    int b = m / NTOK_, p = m - b * NTOK_;
                    C[((long)(b * SEQ_ + 1 + p)) * D_ + n] =
                        vl + rowadd[(long)p * D_ + n];
                }
            }
        }
    }
}

// ---------------- fused flash attention (fp32) -------------------------------
// grid: (ceil(S/64), B*H); block: 256 threads = 16x16, 4x4 micro-tile.
// q,k,v in (B,H,S,DH); ctx out (B,S,D). Exact softmax (online, running max).
#define FSM 68
#define NKV 15        // ceil(912/64)

__global__ __launch_bounds__(256) void flash_k(
    const float* __restrict__ q, const float* __restrict__ kg,
    const float* __restrict__ vg, float* __restrict__ ctx,
    const int* __restrict__ mask, float scale)
{
    extern __shared__ float smf[];
    float* Qt = smf;                 // [64][FSM] transposed: Qt[k][r]
    float* Kt = Qt + 64 * FSM;       // [64][FSM] transposed: Kt[k][c]
    float* Vs = Kt + 64 * FSM;       // [64][FSM] natural:    Vs[j][k]
    float* Ps = Vs + 64 * FSM;       // [64][FSM] natural:    Ps[r][j]

    const int tid = threadIdx.x;
    const int tx = tid & 15;
    const int ty = tid >> 4;
    const int z = blockIdx.y;
    const int b = z >> 3;
    const int h = z & 7;
    const int q0 = blockIdx.x * 64;
    const long base = (long)z * SEQ_ * DH_;
    const int mbase = b * SEQ_;

    // load Q tile, transposed into smem
#pragma unroll
    for (int p = 0; p < 16; p++) {
        int idx = tid + p * 256;
        int i = idx >> 6, kk = idx & 63;
        int s = q0 + i;
        Qt[kk * FSM + i] = (s < SEQ_) ? q[base + (long)s * DH_ + kk] : 0.f;
    }

    float m[4], l[4], acc[4][4];
#pragma unroll
    for (int i = 0; i < 4; i++) {
        m[i] = -1e30f; l[i] = 0.f;
#pragma unroll
        for (int j = 0; j < 4; j++) acc[i][j] = 0.f;
    }

    for (int t0 = 0; t0 < NKV; t0++) {
        const int j0 = t0 * 64;
        __syncthreads();   // previous PV reads done before K/V overwrite
#pragma unroll
        for (int p = 0; p < 16; p++) {
            int idx = tid + p * 256;
            int jj = idx >> 6, kk = idx & 63;
            int s = j0 + jj;
            float kvld = 0.f, vvld = 0.f;
            if (s < SEQ_) {
                kvld = kg[base + (long)s * DH_ + kk];
                vvld = vg[base + (long)s * DH_ + kk];
            }
            Kt[kk * FSM + jj] = kvld;
            Vs[jj * FSM + kk] = vvld;
        }
        __syncthreads();

        // S = Q K^T (4x4 per thread)
        float sc[4][4];
#pragma unroll
        for (int i = 0; i < 4; i++)
#pragma unroll
            for (int j = 0; j < 4; j++) sc[i][j] = 0.f;
#pragma unroll 8
        for (int kk = 0; kk < 64; kk++) {
            float4 a4 = *(const float4*)(Qt + kk * FSM + ty * 4);
            float4 b4 = *(const float4*)(Kt + kk * FSM + tx * 4);
            float av[4] = {a4.x, a4.y, a4.z, a4.w};
            float bv[4] = {b4.x, b4.y, b4.z, b4.w};
#pragma unroll
            for (int i = 0; i < 4; i++)
#pragma unroll
                for (int j = 0; j < 4; j++) sc[i][j] += av[i] * bv[j];
        }

        // scale + mask
#pragma unroll
        for (int j = 0; j < 4; j++) {
            int jg = j0 + tx * 4 + j;
            bool ok = (jg < SEQ_) && (mask[mbase + jg] != 0);
#pragma unroll
            for (int i = 0; i < 4; i++)
                sc[i][j] = ok ? sc[i][j] * scale : -1e9f;
        }

        // row max across 16 lanes (tx)
        float rm[4];
#pragma unroll
        for (int i = 0; i < 4; i++) {
            float v0 = fmaxf(fmaxf(sc[i][0], sc[i][1]), fmaxf(sc[i][2], sc[i][3]));
#pragma unroll
            for (int o = 8; o > 0; o >>= 1)
                v0 = fmaxf(v0, __shfl_xor_sync(0xffffffffu, v0, o));
            rm[i] = v0;
        }

        float corr[4], rs[4];
#pragma unroll
        for (int i = 0; i < 4; i++) {
            float mn = fmaxf(m[i], rm[i]);
            corr[i] = expf(m[i] - mn);
            m[i] = mn;
            rs[i] = 0.f;
        }

        // p = exp(s - m), stash to smem (float4 rows), row sums
#pragma unroll
        for (int i = 0; i < 4; i++) {
            float p0 = expf(sc[i][0] - m[i]);
            float p1 = expf(sc[i][1] - m[i]);
            float p2 = expf(sc[i][2] - m[i]);
            float p3 = expf(sc[i][3] - m[i]);
            rs[i] = (p0 + p1) + (p2 + p3);
            *(float4*)(Ps + (ty * 4 + i) * FSM + tx * 4) =
                make_float4(p0, p1, p2, p3);
        }
#pragma unroll
        for (int i = 0; i < 4; i++) {
            float v0 = rs[i];
#pragma unroll
            for (int o = 8; o > 0; o >>= 1)
                v0 += __shfl_xor_sync(0xffffffffu, v0, o);
            l[i] = l[i] * corr[i] + v0;
#pragma unroll
            for (int j = 0; j < 4; j++) acc[i][j] *= corr[i];
        }
        __syncthreads();

        // acc += P V
#pragma unroll 8
        for (int kk = 0; kk < 64; kk++) {
            float4 v4 = *(const float4*)(Vs + kk * FSM + tx * 4);
            float vv[4] = {v4.x, v4.y, v4.z, v4.w};
#pragma unroll
            for (int i = 0; i < 4; i++) {
                float pv = Ps[(ty * 4 + i) * FSM + kk];
#pragma unroll
                for (int j = 0; j < 4; j++) acc[i][j] += pv * vv[j];
            }
        }
    }

    // write O = acc / l  to ctx (B,S,D)
#pragma unroll
    for (int i = 0; i < 4; i++) {
        int s = q0 + ty * 4 + i;
        if (s >= SEQ_) continue;
        float inv = 1.f / l[i];
        float4 o4 = make_float4(acc[i][0] * inv, acc[i][1] * inv,
                                acc[i][2] * inv, acc[i][3] * inv);
        *(float4*)(ctx + ((long)(b * SEQ_ + s)) * D_ + h * DH_ + tx * 4) = o4;
    }
}

// ---------------- feature transpose (B,CIN,HW) -> rows of g_A (tok, CIN) ----
__global__ void transpose_feat_k(const float* __restrict__ feat,
                                 float* __restrict__ Aout,
                                 int HW, int tokoff)
{
    __shared__ float tile[32][33];
    const int b = blockIdx.z;
    const int hw0 = blockIdx.x * 32;
    const int c0 = blockIdx.y * 32;
    const int tx = threadIdx.x, ty = threadIdx.y;

    const float* fb = feat + ((long)b * CIN_ + c0) * HW;
#pragma unroll
    for (int i = ty; i < 32; i += 8) {
        int hw = hw0 + tx;
        tile[i][tx] = (hw < HW) ? fb[(long)i * HW + hw] : 0.f;
    }
    __syncthreads();
#pragma unroll
    for (int i = ty; i < 32; i += 8) {
        int hw = hw0 + i;
        if (hw < HW)
            Aout[((long)(b * NTOK_ + tokoff + hw)) * CIN_ + c0 + tx] = tile[tx][i];
    }
}

__global__ void addvec_k(const float* __restrict__ conv_b,
                         const float* __restrict__ org_emb,
                         const float* __restrict__ r1_emb,
                         const float* __restrict__ r2_emb,
                         const float* __restrict__ pos_emb,
                         float* __restrict__ addv)
{
    int p = blockIdx.x;
    int d = threadIdx.x;
    int ti, tj;
    const float* emb;
    if (p < 768) {
        int h = p / 32, w = p - h * 32;
        ti = h * 10 / 24; tj = w * 10 / 32; emb = org_emb;
    } else if (p < 876) {
        int pp = p - 768;
        int h = pp / 12, w = pp - h * 12;
        ti = h * 10 / 9; tj = w * 10 / 12; emb = r1_emb;
    } else {
        int pp = p - 876;
        int h = pp / 7, w = pp - h * 7;
        ti = h * 10 / 5; tj = w * 10 / 7; emb = r2_emb;
    }
    addv[(long)p * D_ + d] = conv_b[d] + emb[d] + pos_emb[((long)ti * 10 + tj) * D_ + d];
}

__global__ void cls_k(const float* __restrict__ cls_token, float* __restrict__ x)
{
    int b = blockIdx.x, d = threadIdx.x;
    x[((long)b * SEQ_) * D_ + d] = cls_token[d];
}

// ---------------- layernorm over D=512 ---------------------------------------
__global__ void ln_k(const float* __restrict__ in, float* __restrict__ out,
                     const float* __restrict__ g, const float* __restrict__ bb)
{
    long t = blockIdx.x;
    const float* x = in + t * D_;
    float* o = out + t * D_;
    int tid = threadIdx.x;
    __shared__ float sm[256];

    float s = 0.f;
    for (int i = tid; i < D_; i += 256) s += x[i];
    sm[tid] = s; __syncthreads();
    for (int k = 128; k > 0; k >>= 1) {
        if (tid < k) sm[tid] += sm[tid + k];
        __syncthreads();
    }
    float mean = sm[0] * (1.f / D_); __syncthreads();

    float v = 0.f;
    for (int i = tid; i < D_; i += 256) {
        float d = x[i] - mean;
        v += d * d;
    }
    sm[tid] = v; __syncthreads();
    for (int k = 128; k > 0; k >>= 1) {
        if (tid < k) sm[tid] += sm[tid + k];
        __syncthreads();
    }
    float rstd = rsqrtf(sm[0] * (1.f / D_) + 1e-6f);
    for (int i = tid; i < D_; i += 256)
        o[i] = (x[i] - mean) * rstd * g[i] + bb[i];
}

// ---------------- MLP head on cls token --------------------------------------
__global__ void head_k(const float* __restrict__ x,
                       const float* __restrict__ w1,
                       const float* __restrict__ w2,
                       float* __restrict__ out)
{
    int b = blockIdx.x;
    int tid = threadIdx.x;
    __shared__ float cls[D_];
    __shared__ float red[256];
    for (int i = tid; i < D_; i += 256)
        cls[i] = x[((long)b * SEQ_) * D_ + i];
    __syncthreads();

    float partial = 0.f;
    for (int j = tid; j < DMLP_; j += 256) {
        const float* w = w1 + (long)j * D_;
        float s = 0.f;
#pragma unroll 8
        for (int k = 0; k < D_; k++) s += cls[k] * w[k];
        partial += gelu_exact(s) * w2[j];
    }
    red[tid] = partial; __syncthreads();
    for (int k = 128; k > 0; k >>= 1) {
        if (tid < k) red[tid] += red[tid + k];
        __syncthreads();
    }
    if (tid == 0) out[b] = red[0];
}

// =============================================================================
extern "C" void kernel_launch(void* const* d_in, const int* in_sizes, int n_in,
                              void* d_out, int out_size)
{
    const float* feat_org = (const float*)d_in[0];
    const float* feat_r1  = (const float*)d_in[1];
    const float* feat_r2  = (const float*)d_in[2];
    const float* conv_w   = (const float*)d_in[3];
    const float* conv_b   = (const float*)d_in[4];
    const float* org_emb  = (const float*)d_in[5];
    const float* r1_emb   = (const float*)d_in[6];
    const float* r2_emb   = (const float*)d_in[7];
    const float* pos_emb  = (const float*)d_in[8];
    const float* cls_tok  = (const float*)d_in[9];
    const float* Wq = (const float*)d_in[10];
    const float* bq = (const float*)d_in[11];
    const float* Wk = (const float*)d_in[12];
    const float* bk = (const float*)d_in[13];
    const float* Wv = (const float*)d_in[14];
    const float* bv = (const float*)d_in[15];
    const float* Wo = (const float*)d_in[16];
    const float* bo = (const float*)d_in[17];
    const float* ln1g = (const float*)d_in[18];
    const float* ln1b = (const float*)d_in[19];
    const float* w1 = (const float*)d_in[20];
    const float* b1 = (const float*)d_in[21];
    const float* w2 = (const float*)d_in[22];
    const float* b2 = (const float*)d_in[23];
    const float* ln2g = (const float*)d_in[24];
    const float* ln2b = (const float*)d_in[25];
    const float* pw1 = (const float*)d_in[26];
    const float* pw2 = (const float*)d_in[27];
    const int*   mask = (const int*)d_in[28];
    float* out = (float*)d_out;

    float *A, *addv, *x, *tmp, *q, *k, *v, *ctx, *ff;
    cudaGetSymbolAddress((void**)&A, g_A);
    cudaGetSymbolAddress((void**)&addv, g_add);
    cudaGetSymbolAddress((void**)&x, g_x);
    cudaGetSymbolAddress((void**)&tmp, g_tmp);
    cudaGetSymbolAddress((void**)&q, g_q);
    cudaGetSymbolAddress((void**)&k, g_k);
    cudaGetSymbolAddress((void**)&v, g_v);
    cudaGetSymbolAddress((void**)&ctx, g_ctx);
    cudaGetSymbolAddress((void**)&ff, g_ff);

    const int flash_smem = 4 * 64 * FSM * (int)sizeof(float);
    cudaFuncSetAttribute(flash_k, cudaFuncAttributeMaxDynamicSharedMemorySize,
                         flash_smem);

    dim3 tb(32, 8);
    transpose_feat_k<<<dim3(24, CIN_ / 32, B_), tb>>>(feat_org, A, 768, 0);
    transpose_feat_k<<<dim3(4,  CIN_ / 32, B_), tb>>>(feat_r1,  A, 108, 768);
    transpose_feat_k<<<dim3(2,  CIN_ / 32, B_), tb>>>(feat_r2,  A, 35,  876);
    addvec_k<<<NTOK_, D_>>>(conv_b, org_emb, r1_emb, r2_emb, pos_emb, addv);

    gemm_tc<128, 7><<<dim3(4, 57, 1), 256>>>(A, conv_w, x, B_ * NTOK_, D_, CIN_,
                                             nullptr, nullptr, addv);
    cls_k<<<B_, D_>>>(cls_tok, x);

    const float scale = 0.125f;  // 1/sqrt(64)
    for (int i = 0; i < L_; i++) {
        const float* wq = Wq + (long)i * D_ * D_;
        const float* wk = Wk + (long)i * D_ * D_;
        const float* wv = Wv + (long)i * D_ * D_;
        const float* wo = Wo + (long)i * D_ * D_;

        gemm_tc<128, 1><<<dim3(4, 57, 1), 256>>>(x, wq, q, B_ * SEQ_, D_, D_,
                                                 bq + i * D_, nullptr, nullptr);
        gemm_tc<128, 1><<<dim3(4, 57, 1), 256>>>(x, wk, k, B_ * SEQ_, D_, D_,
                                                 bk + i * D_, nullptr, nullptr);
        gemm_tc<128, 1><<<dim3(4, 57, 1), 256>>>(x, wv, v, B_ * SEQ_, D_, D_,
                                                 bv + i * D_, nullptr, nullptr);

        flash_k<<<dim3(NKV, B_ * H_), 256, flash_smem>>>(q, k, v, ctx, mask, scale);

        gemm_tc<128, 5><<<dim3(4, 57, 1), 256>>>(ctx, wo, tmp, B_ * SEQ_, D_, D_,
                                                 bo + i * D_, x, nullptr);
        ln_k<<<B_ * SEQ_, 256>>>(tmp, x, ln1g + i * D_, ln1b + i * D_);

        gemm_tc<128, 6><<<dim3(16, 57, 1), 256>>>(x, w1 + (long)i * DFF_ * D_, ff,
                                                  B_ * SEQ_, DFF_, D_,
                                                  b1 + i * DFF_, nullptr, nullptr);
        gemm_tc<128, 5><<<dim3(4, 57, 1), 256>>>(ff, w2 + (long)i * D_ * DFF_, tmp,
                                                 B_ * SEQ_, D_, DFF_,
                                                 b2 + i * D_, x, nullptr);
        ln_k<<<B_ * SEQ_, 256>>>(tmp, x, ln2g + i * D_, ln2b + i * D_);
    }

    head_k<<<B_, 256>>>(x, pw1, pw2, out);
}